// round 14
// baseline (speedup 1.0000x reference)
#include <cuda_runtime.h>

// Blocks_86096914416144 — SNN block scan, R14: R13 body BYTE-IDENTICAL
// (bit-exact numerics, 57.8us class). Two launch-side changes only:
//  1) Uniform warp distribution: 152 CTAs x 224 threads (7 warps) -> exactly
//     one CTA per SM on GB300 (152 SMs). R5/R13's 256x4-warp launch loaded
//     ~104 SMs with 8 warps and ~48 with 4; wall was set by the 8-warp SMs.
//     Excess threads (tid >= 32768) exit; kernel has no barriers -> safe.
//  2) __stcs on the output stores (write-once stream, evict-first in L2).
//     First time isolated from the toxic R3 bundle.

#define T_LEN   1024
#define TB      8
#define NBLK    (T_LEN / TB)      // 128
#define BATCH   32
#define NOUT    1024
#define BN      (BATCH * NOUT)    // 32768
#define CTA     224               // 7 warps
#define NSM     152
#define NCTA    NSM               // one CTA per SM

__global__ __launch_bounds__(CTA)
void blocks_snn_kernel(const float* __restrict__ x,
                       const float* __restrict__ beta_raw,
                       const float* __restrict__ p_raw,
                       const float* __restrict__ b_raw,
                       float* __restrict__ out)
{
    const int tid = blockIdx.x * CTA + threadIdx.x;
    if (tid >= BN) return;                      // 34048 launched, 32768 work
    const int n = tid & (NOUT - 1);

    const float beta  = fminf(fmaxf(beta_raw[n], 0.001f), 0.999f);
    const float p     = fminf(fmaxf(fabsf(p_raw[n]), 0.0f), 0.999f);
    const float bb    = fminf(fmaxf(fabsf(b_raw[n]), 0.001f), 1.0f);
    const float inv_p = 1.0f / p;

    float bpow[TB];
    bpow[0] = 1.0f;
    #pragma unroll
    for (int k = 1; k < TB; k++) bpow[k] = powf(beta, (float)k);

    float ppow[TB + 1];
    ppow[0] = 1.0f;
    #pragma unroll
    for (int k = 1; k <= TB; k++) ppow[k] = powf(p, (float)k);

    // carry state (exact R5/R13)
    float z[TB];
    #pragma unroll
    for (int t = 0; t < TB; t++) z[t] = 0.0f;
    float a    = 0.0f;
    float vmem = 0.0f;

    const float* xp = x + tid;
    float*       op = out + tid;

    // 4-slot register ring, prefetch 3 blocks ahead (exact R5/R13)
    float buf[4][TB];
    #pragma unroll
    for (int pb = 0; pb < 3; pb++) {
        const float* xb = xp + (size_t)pb * TB * BN;
        #pragma unroll
        for (int t = 0; t < TB; t++) buf[pb][t] = xb[t * BN];
    }

    #pragma unroll 1
    for (int g = 0; g < NBLK / 4; g++) {
        #pragma unroll
        for (int u = 0; u < 4; u++) {
            const int blk = 4 * g + u;

            if (blk + 3 < NBLK) {
                const float* xb = xp + (size_t)(blk + 3) * TB * BN;
                #pragma unroll
                for (int t = 0; t < TB; t++)
                    buf[(u + 3) & 3][t] = xb[t * BN];
            }
            const float* xc = buf[u & 3];

            // ---- head: sg, maskf, ds from z (exact R5) ----
            float sg[TB];
            float maskf = 0.0f;
            #pragma unroll
            for (int t = 0; t < TB; t++) {
                sg[t] = (z[t] == 1.0f) ? 1.0f : 0.0f;
                if (sg[t] != 0.0f) maskf = 1.0f;
            }

            float a_at = 0.0f;
            #pragma unroll
            for (int t = 0; t < TB; t++)
                if (sg[t] != 0.0f) a_at += ppow[t + 1] * a;
            a_at += inv_p;

            int ds = 0;
            #pragma unroll
            for (int t = 0; t < TB; t++)
                if (z[t] > 1.0f) ds++;

            float pds = ppow[0];
            #pragma unroll
            for (int k = 1; k <= TB; k++)
                if (ds == k) pds = ppow[k];

            const float new_a = a_at * pds;
            a = (maskf != 0.0f) ? new_a : (ppow[TB] * a);

            // ---- refractory masking + carry-in (exact R5) ----
            const float v_init = vmem * (1.0f - maskf);
            float cur[TB];
            #pragma unroll
            for (int t = 0; t < TB; t++)
                cur[t] = (z[t] < maskf) ? 0.0f : xc[t];
            cur[0] = cur[0] + beta * v_init;

            // ---- causal decayed sums, s-major (bit-identical per-t order) ----
            float m[TB];
            #pragma unroll
            for (int t = 0; t < TB; t++) m[t] = 0.0f;
            #pragma unroll
            for (int s = 0; s < TB; s++) {
                #pragma unroll
                for (int t = s; t < TB; t++)
                    m[t] += bpow[t - s] * cur[s];
            }

            // ---- threshold (exact R5) ----
            float f[TB];
            #pragma unroll
            for (int t = 0; t < TB; t++) {
                const float vth = 1.0f + bb * (ppow[t + 1] * a);
                f[t] = ((m[t] - vth) > 0.0f) ? 1.0f : 0.0f;
            }
            const float mlast = m[TB - 1];

            // ---- z = double cumsum; emit spikes (streaming stores) ----
            float* ob = op + (size_t)blk * TB * BN;
            float c = 0.0f, zr = 0.0f;
            #pragma unroll
            for (int t = 0; t < TB; t++) {
                c  += f[t];
                zr += c;
                z[t] = zr;
                __stcs(ob + t * BN, (zr == 1.0f) ? 1.0f : 0.0f);
            }

            vmem = mlast;
        }
    }
}

extern "C" void kernel_launch(void* const* d_in, const int* in_sizes, int n_in,
                              void* d_out, int out_size)
{
    const float* x        = (const float*)d_in[0];
    const float* beta_raw = (const float*)d_in[1];
    const float* p_raw    = (const float*)d_in[2];
    const float* b_raw    = (const float*)d_in[3];
    float* out = (float*)d_out;

    blocks_snn_kernel<<<NCTA, CTA>>>(x, beta_raw, p_raw, b_raw, out);
}